// round 5
// baseline (speedup 1.0000x reference)
#include <cuda_runtime.h>
#include <cstdint>

// DiceLoss (57-bin label histogram) for B200 sm_100a — R5.
//
// R4 was issue+smem-op bound (~20 instr, 6 smem ops per pair). R5 fuses the
// three histograms into ONE u32 counter word per label per lane:
//     word[v] : byte0 = cnt_pred[v], byte1 = cnt_true[v], byte2 = inter[v]
// Per pair (p,t):
//     word[p] += (p==t) ? 0x010101 : 0x000001
//     word[t] += (p==t) ? 0        : 0x000100
// If p==t both updates address the SAME word: we load both values first, then
// store the T-word BEFORE the P-word, so the P store (carrying the full
// combined increment on top of the original value) lands last -> exact.
// Max increments per byte per lane = pairs/thread ~= 120 < 255: no carries.
//
// Layout: counter v of lane l in warp w at word sh[w*1824 + v*32 + l]
// -> bank == l for any v (conflict-free, data-independent) and the address is
// one IMAD. Per pair: 2 IMAD + ISETP + 2 SEL + 2 LDS + 2 IADD + 2 STS = 11
// instr, 4 smem wavefronts (was 20/6).
//
// TPB=480 (15 warps), smem 109.4KB+hist -> 2 CTAs/SM (30 warps).
// Cross-warp combine: staggered shared atomicAdd into a 171-int block hist
// (different warps on different counters at any time -> no contention), then
// last-arriving block folds per-block partials and writes the scalar loss.

#define NBINS   57
#define NB3     171
#define TPB     480
#define NWARPS  15
#define WPW     (NBINS * 32)                  // words per warp region = 1824
#define CNT_WORDS   (NWARPS * WPW)            // 27,360
#define SMEM_WORDS  (CNT_WORDS + NB3)         // + block hist
#define SMEM_BYTES  (SMEM_WORDS * 4)          // 110,124 B -> 2 CTAs/SM
#define MAXBLK  512

__device__ int g_part[NB3 * MAXBLK];          // [counter][block]
__device__ unsigned int g_arrive = 0;         // self-resets each launch

__device__ __forceinline__ void proc(int* wl, int p, int t) {
    int* aP = wl + (p << 5);
    int* aT = wl + (t << 5);
    bool m = (p == t);
    int incP = m ? 0x010101 : 0x000001;
    int incT = m ? 0        : 0x000100;
    int vP = *aP;
    int vT = *aT;
    *aT = vT + incT;          // T first: on p==t this is overwritten by the
    *aP = vP + incP;          // P store, which carries the full increment.
}

__device__ __forceinline__ void proc4(int* wl, int4 a, int4 b) {
    proc(wl, a.x, b.x);
    proc(wl, a.y, b.y);
    proc(wl, a.z, b.z);
    proc(wl, a.w, b.w);
}

extern "C" __global__ void __launch_bounds__(TPB, 2)
hist_kernel(const int* __restrict__ pred, const int* __restrict__ targ, int n,
            float* __restrict__ out)
{
    extern __shared__ int sh[];
    int* sh_blk = sh + CNT_WORDS;             // [NB3] block-level histogram

    const int tid  = threadIdx.x;
    const int lane = tid & 31;
    const int warp = tid >> 5;
    int* wl = sh + warp * WPW + lane;         // counter v at wl[v*32]

    for (int i = tid; i < SMEM_WORDS; i += TPB) sh[i] = 0;
    __syncthreads();

    const int stride = gridDim.x * TPB;

    const bool aligned = ((((uintptr_t)pred) | ((uintptr_t)targ)) & 15u) == 0;
    if (aligned) {
        const int n4 = n >> 2;
        const int4* __restrict__ p4 = (const int4*)pred;
        const int4* __restrict__ t4 = (const int4*)targ;
        int i = blockIdx.x * TPB + tid;

        // 4 int4-pairs per trip; all 8 LDG.128 batched before histogram work.
        for (; i + 3 * stride < n4; i += 4 * stride) {
            int4 a0 = __ldg(p4 + i);
            int4 a1 = __ldg(p4 + i + stride);
            int4 a2 = __ldg(p4 + i + 2 * stride);
            int4 a3 = __ldg(p4 + i + 3 * stride);
            int4 b0 = __ldg(t4 + i);
            int4 b1 = __ldg(t4 + i + stride);
            int4 b2 = __ldg(t4 + i + 2 * stride);
            int4 b3 = __ldg(t4 + i + 3 * stride);
            proc4(wl, a0, b0);
            proc4(wl, a1, b1);
            proc4(wl, a2, b2);
            proc4(wl, a3, b3);
        }
        for (; i < n4; i += stride) {
            int4 a = __ldg(p4 + i);
            int4 b = __ldg(t4 + i);
            proc4(wl, a, b);
        }
        for (int j = (n4 << 2) + blockIdx.x * TPB + tid; j < n; j += stride)
            proc(wl, __ldg(pred + j), __ldg(targ + j));
    } else {
        for (int i = blockIdx.x * TPB + tid; i < n; i += stride)
            proc(wl, __ldg(pred + i), __ldg(targ + i));
    }
    __syncthreads();

    // Per-warp lane reduction. Split-mask REDUX: bytes 0+2 summed in one
    // reduction (each gets a 16-bit field), byte1 in a second. Then lane0
    // adds into the block hist via shared atomics; warps start at staggered
    // counters so no two warps hit the same address at the same time.
    for (int j = 0; j < NBINS; j++) {
        int c = j + warp * 4;
        if (c >= NBINS) c -= NBINS;
        if (c >= NBINS) c -= NBINS;           // warp*4 max 56 -> c < 113
        unsigned int v = (unsigned int)wl[c << 5];
        unsigned int r02 = (unsigned int)__reduce_add_sync(0xffffffffu, (int)(v & 0x00FF00FFu));
        unsigned int r1  = (unsigned int)__reduce_add_sync(0xffffffffu, (int)((v >> 8) & 0xFFu));
        if (lane == 0) {
            atomicAdd(&sh_blk[c],             (int)(r02 & 0xFFFFu));   // pred
            atomicAdd(&sh_blk[NBINS + c],     (int)r1);                // true
            atomicAdd(&sh_blk[2 * NBINS + c], (int)(r02 >> 16));       // inter
        }
    }
    __syncthreads();

    if (tid < NB3)
        g_part[tid * MAXBLK + blockIdx.x] = sh_blk[tid];
    __syncthreads();

    // ---- fused finalize: last block folds all partials ----
    __shared__ int is_last;
    __threadfence();
    if (tid == 0) {
        unsigned int old = atomicAdd(&g_arrive, 1u);
        is_last = (old == gridDim.x - 1) ? 1 : 0;
    }
    __syncthreads();
    if (!is_last) return;
    __threadfence();

    int*   hh   = sh;                         // counter region is dead now
    float* dsum = (float*)(sh + 256);
    const int nblocks = gridDim.x;

    for (int c = warp; c < NB3; c += NWARPS) {
        int s = 0;
        for (int b = lane; b < nblocks; b += 32)
            s += g_part[c * MAXBLK + b];
        s = __reduce_add_sync(0xffffffffu, s);
        if (lane == 0) hh[c] = s;
    }
    __syncthreads();

    if (tid < 64) {
        float v = 0.0f;
        if (tid >= 1 && tid < NBINS) {
            float inter = (float)hh[2 * NBINS + tid];
            float uni   = (float)hh[tid] + (float)hh[NBINS + tid];
            v = 2.0f * inter / (uni + 1e-5f);
        }
        dsum[tid] = v;
    }
    __syncthreads();

    if (tid == 0) {
        float s = 0.0f;
        #pragma unroll
        for (int i = 0; i < 64; i++) s += dsum[i];
        out[0] = 1.0f - s / (float)(NBINS - 1);
        g_arrive = 0;                         // ready for next graph replay
    }
}

extern "C" void kernel_launch(void* const* d_in, const int* in_sizes, int n_in,
                              void* d_out, int out_size)
{
    const int* pred = (const int*)d_in[0];
    const int* targ = (const int*)d_in[1];
    const int n = in_sizes[0];

    cudaFuncSetAttribute((const void*)hist_kernel,
                         cudaFuncAttributeMaxDynamicSharedMemorySize, SMEM_BYTES);

    int sms = 148;
    if (cudaDeviceGetAttribute(&sms, cudaDevAttrMultiProcessorCount, 0) != cudaSuccess)
        sms = 148;
    int grid = 2 * sms;
    if (grid > MAXBLK) grid = MAXBLK;
    if (grid < 1) grid = 1;

    hist_kernel<<<grid, TPB, SMEM_BYTES>>>(pred, targ, n, (float*)d_out);
}

// round 8
// speedup vs baseline: 1.0069x; 1.0069x over previous
#include <cuda_runtime.h>
#include <cstdint>

// DiceLoss (57-bin label histogram) for B200 sm_100a — R6 kernel, third
// submission (two consecutive GB300 container/broker failures; kernel itself
// is untested and unchanged to preserve attribution).
//
// R5 showed a phase-locked loop: [LDG burst + 600cyc wait] then [smem RMW
// crunch] with zero overlap (DRAM 33%, issue 38%, nothing saturated). ptxas
// cannot hoist the next loads above the data-dependent STS chain, so R6 does
// it manually: two-stage register pipeline — load batch i+1 BEFORE processing
// batch i. DRAM latency/transfer now overlaps the histogram crunch.
//
// Histogram core (unchanged from R5): one u32 counter word per label per lane,
//   word[v]: byte0=cnt_pred, byte1=cnt_true, byte2=inter
//   pair (p,t):  word[p] += (p==t) ? 0x010101 : 1;  word[t] += (p==t) ? 0 : 0x100
//   (T stored first; on p==t the P store carries the combined increment.)
// Layout word index v*32+lane -> bank==lane, conflict-free, one-IMAD address.
// Max increments per byte per lane ~= 120 < 255: no carries.

#define NBINS   57
#define NB3     171
#define TPB     480
#define NWARPS  15
#define WPW     (NBINS * 32)                  // words per warp region = 1824
#define CNT_WORDS   (NWARPS * WPW)            // 27,360
#define SMEM_WORDS  (CNT_WORDS + NB3)
#define SMEM_BYTES  (SMEM_WORDS * 4)          // ~110 KB -> 2 CTAs/SM
#define MAXBLK  512

__device__ int g_part[NB3 * MAXBLK];          // [counter][block]
__device__ unsigned int g_arrive = 0;         // self-resets each launch

__device__ __forceinline__ void proc(int* wl, int p, int t) {
    int* aP = wl + (p << 5);
    int* aT = wl + (t << 5);
    bool m = (p == t);
    int incP = m ? 0x010101 : 0x000001;
    int incT = m ? 0        : 0x000100;
    int vP = *aP;
    int vT = *aT;
    *aT = vT + incT;          // T first; P store lands last and is exact on p==t
    *aP = vP + incP;
}

__device__ __forceinline__ void proc4(int* wl, int4 a, int4 b) {
    proc(wl, a.x, b.x);
    proc(wl, a.y, b.y);
    proc(wl, a.z, b.z);
    proc(wl, a.w, b.w);
}

extern "C" __global__ void __launch_bounds__(TPB, 2)
hist_kernel(const int* __restrict__ pred, const int* __restrict__ targ, int n,
            float* __restrict__ out)
{
    extern __shared__ int sh[];
    int* sh_blk = sh + CNT_WORDS;

    const int tid  = threadIdx.x;
    const int lane = tid & 31;
    const int warp = tid >> 5;
    int* wl = sh + warp * WPW + lane;

    for (int i = tid; i < SMEM_WORDS; i += TPB) sh[i] = 0;
    __syncthreads();

    const int stride = gridDim.x * TPB;

    const bool aligned = ((((uintptr_t)pred) | ((uintptr_t)targ)) & 15u) == 0;
    if (aligned) {
        const int n4 = n >> 2;
        const int4* __restrict__ p4 = (const int4*)pred;
        const int4* __restrict__ t4 = (const int4*)targ;
        const int step = 2 * stride;
        int i = blockIdx.x * TPB + tid;

        if (i + stride < n4) {
            // ---- software-pipelined main loop (2 int4-pairs per stage) ----
            int4 a0 = __ldg(p4 + i);
            int4 a1 = __ldg(p4 + i + stride);
            int4 b0 = __ldg(t4 + i);
            int4 b1 = __ldg(t4 + i + stride);
            for (i += step; i + stride < n4; i += step) {
                // next batch issued BEFORE current crunch -> DRAM overlaps smem
                int4 na0 = __ldg(p4 + i);
                int4 na1 = __ldg(p4 + i + stride);
                int4 nb0 = __ldg(t4 + i);
                int4 nb1 = __ldg(t4 + i + stride);
                proc4(wl, a0, b0);
                proc4(wl, a1, b1);
                a0 = na0; a1 = na1; b0 = nb0; b1 = nb1;
            }
            proc4(wl, a0, b0);
            proc4(wl, a1, b1);
        }
        // remainder int4 batches
        for (; i < n4; i += stride) {
            int4 a = __ldg(p4 + i);
            int4 b = __ldg(t4 + i);
            proc4(wl, a, b);
        }
        // scalar tail
        for (int j = (n4 << 2) + blockIdx.x * TPB + tid; j < n; j += stride)
            proc(wl, __ldg(pred + j), __ldg(targ + j));
    } else {
        for (int i = blockIdx.x * TPB + tid; i < n; i += stride)
            proc(wl, __ldg(pred + i), __ldg(targ + i));
    }
    __syncthreads();

    // Per-warp lane reduction: split-mask REDUX (bytes 0+2 in one reduction,
    // byte1 in another), staggered shared atomics into the block histogram.
    for (int j = 0; j < NBINS; j++) {
        int c = j + warp * 4;
        if (c >= NBINS) c -= NBINS;
        if (c >= NBINS) c -= NBINS;
        unsigned int v = (unsigned int)wl[c << 5];
        unsigned int r02 = (unsigned int)__reduce_add_sync(0xffffffffu, (int)(v & 0x00FF00FFu));
        unsigned int r1  = (unsigned int)__reduce_add_sync(0xffffffffu, (int)((v >> 8) & 0xFFu));
        if (lane == 0) {
            atomicAdd(&sh_blk[c],             (int)(r02 & 0xFFFFu));   // pred
            atomicAdd(&sh_blk[NBINS + c],     (int)r1);                // true
            atomicAdd(&sh_blk[2 * NBINS + c], (int)(r02 >> 16));       // inter
        }
    }
    __syncthreads();

    if (tid < NB3)
        g_part[tid * MAXBLK + blockIdx.x] = sh_blk[tid];
    __syncthreads();

    // ---- fused finalize: last block folds all partials ----
    __shared__ int is_last;
    __threadfence();
    if (tid == 0) {
        unsigned int old = atomicAdd(&g_arrive, 1u);
        is_last = (old == gridDim.x - 1) ? 1 : 0;
    }
    __syncthreads();
    if (!is_last) return;
    __threadfence();

    int*   hh   = sh;
    float* dsum = (float*)(sh + 256);
    const int nblocks = gridDim.x;

    for (int c = warp; c < NB3; c += NWARPS) {
        int s = 0;
        for (int b = lane; b < nblocks; b += 32)
            s += g_part[c * MAXBLK + b];
        s = __reduce_add_sync(0xffffffffu, s);
        if (lane == 0) hh[c] = s;
    }
    __syncthreads();

    if (tid < 64) {
        float v = 0.0f;
        if (tid >= 1 && tid < NBINS) {
            float inter = (float)hh[2 * NBINS + tid];
            float uni   = (float)hh[tid] + (float)hh[NBINS + tid];
            v = 2.0f * inter / (uni + 1e-5f);
        }
        dsum[tid] = v;
    }
    __syncthreads();

    if (tid == 0) {
        float s = 0.0f;
        #pragma unroll
        for (int i = 0; i < 64; i++) s += dsum[i];
        out[0] = 1.0f - s / (float)(NBINS - 1);
        g_arrive = 0;
    }
}

extern "C" void kernel_launch(void* const* d_in, const int* in_sizes, int n_in,
                              void* d_out, int out_size)
{
    const int* pred = (const int*)d_in[0];
    const int* targ = (const int*)d_in[1];
    const int n = in_sizes[0];

    cudaFuncSetAttribute((const void*)hist_kernel,
                         cudaFuncAttributeMaxDynamicSharedMemorySize, SMEM_BYTES);

    int sms = 148;
    if (cudaDeviceGetAttribute(&sms, cudaDevAttrMultiProcessorCount, 0) != cudaSuccess)
        sms = 148;
    int grid = 2 * sms;
    if (grid > MAXBLK) grid = MAXBLK;
    if (grid < 1) grid = 1;

    hist_kernel<<<grid, TPB, SMEM_BYTES>>>(pred, targ, n, (float*)d_out);
}

// round 9
// speedup vs baseline: 1.0473x; 1.0402x over previous
#include <cuda_runtime.h>
#include <cstdint>

// DiceLoss (57-bin label histogram) for B200 sm_100a — R9.
//
// Evidence R2..R8: BW insensitive to occupancy & sw-pipelining; best was
// 1 CTA/SM, grid=148, 8 batched LDG.128 (3.2 TB/s). All pipes 30-45% =>
// latency-bound with too few bytes in flight per warp. R9:
//   - 16 LDG.128 batched per trip (8KB/warp in flight; 128KB/SM at 16 warps)
//   - fused 10-bit-field counters: word[v] = pred(0-9)|true(10-19)|inter(20-29)
//     pair (p,t): word[p] += (p==t) ? 0x100401 : 1; word[t] += (p==t) ? 0 : 0x400
//     (T stored first; on p==t the P store carries the combined increment.)
//     max 222 increments/field/lane < 1023 -> no carries.
//   - layout word v*32+lane -> bank==lane (conflict-free, one-IMAD address)
//   - grid=148, TPB=512, 1 CTA/SM (117KB counters + scratch)

#define NBINS   57
#define NB3     171
#define TPB     512
#define NWARPS  16
#define WPW     (NBINS * 32)                  // 1824 words per warp region
#define CNT_WORDS   (NWARPS * WPW)            // 29,184
#define SCRATCH_WORDS (NWARPS * NB3)          // 2736
#define SMEM_WORDS  (CNT_WORDS + SCRATCH_WORDS)
#define SMEM_BYTES  (SMEM_WORDS * 4)          // 127,680 B -> 1 CTA/SM
#define MAXBLK  256

__device__ int g_part[NB3 * MAXBLK];          // [counter][block]
__device__ unsigned int g_arrive = 0;         // self-resets each launch

__device__ __forceinline__ void proc(int* wl, int p, int t) {
    int* aP = wl + (p << 5);
    int* aT = wl + (t << 5);
    bool m = (p == t);
    int incP = m ? 0x100401 : 0x000001;       // pred+true+inter  |  pred only
    int incT = m ? 0        : 0x000400;       // nothing          |  true only
    int vP = *aP;
    int vT = *aT;
    *aT = vT + incT;      // T first; on p==t the P store (below) lands last
    *aP = vP + incP;      // carrying the full combined increment -> exact.
}

__device__ __forceinline__ void proc4(int* wl, int4 a, int4 b) {
    proc(wl, a.x, b.x);
    proc(wl, a.y, b.y);
    proc(wl, a.z, b.z);
    proc(wl, a.w, b.w);
}

extern "C" __global__ void __launch_bounds__(TPB, 1)
hist_kernel(const int* __restrict__ pred, const int* __restrict__ targ, int n,
            float* __restrict__ out)
{
    extern __shared__ int sh[];
    int* scratch = sh + CNT_WORDS;

    const int tid  = threadIdx.x;
    const int lane = tid & 31;
    const int warp = tid >> 5;
    int* wl = sh + warp * WPW + lane;

    for (int i = tid; i < SMEM_WORDS; i += TPB) sh[i] = 0;
    __syncthreads();

    const int stride = gridDim.x * TPB;

    const bool aligned = ((((uintptr_t)pred) | ((uintptr_t)targ)) & 15u) == 0;
    if (aligned) {
        const int n4 = n >> 2;
        const int4* __restrict__ p4 = (const int4*)pred;
        const int4* __restrict__ t4 = (const int4*)targ;
        int i = blockIdx.x * TPB + tid;

        // 8 int4-pairs per trip: ALL 16 LDG.128 issued before any smem work.
        // 8KB per warp in flight -> latency fully covered at 16 warps/SM.
        for (; i + 7 * stride < n4; i += 8 * stride) {
            int4 a0 = __ldg(p4 + i);
            int4 a1 = __ldg(p4 + i + stride);
            int4 a2 = __ldg(p4 + i + 2 * stride);
            int4 a3 = __ldg(p4 + i + 3 * stride);
            int4 a4 = __ldg(p4 + i + 4 * stride);
            int4 a5 = __ldg(p4 + i + 5 * stride);
            int4 a6 = __ldg(p4 + i + 6 * stride);
            int4 a7 = __ldg(p4 + i + 7 * stride);
            int4 b0 = __ldg(t4 + i);
            int4 b1 = __ldg(t4 + i + stride);
            int4 b2 = __ldg(t4 + i + 2 * stride);
            int4 b3 = __ldg(t4 + i + 3 * stride);
            int4 b4 = __ldg(t4 + i + 4 * stride);
            int4 b5 = __ldg(t4 + i + 5 * stride);
            int4 b6 = __ldg(t4 + i + 6 * stride);
            int4 b7 = __ldg(t4 + i + 7 * stride);
            proc4(wl, a0, b0);
            proc4(wl, a1, b1);
            proc4(wl, a2, b2);
            proc4(wl, a3, b3);
            proc4(wl, a4, b4);
            proc4(wl, a5, b5);
            proc4(wl, a6, b6);
            proc4(wl, a7, b7);
        }
        for (; i < n4; i += stride) {
            int4 a = __ldg(p4 + i);
            int4 b = __ldg(t4 + i);
            proc4(wl, a, b);
        }
        for (int j = (n4 << 2) + blockIdx.x * TPB + tid; j < n; j += stride)
            proc(wl, __ldg(pred + j), __ldg(targ + j));
    } else {
        for (int i = blockIdx.x * TPB + tid; i < n; i += stride)
            proc(wl, __ldg(pred + i), __ldg(targ + i));
    }
    __syncthreads();

    // Per-warp lane reduction: 3 masked REDUX per counter (fields must be
    // isolated before summing: 32*222 = 7104 needs 13 bits).
    for (int c = 0; c < NBINS; c++) {
        unsigned int v = (unsigned int)wl[c << 5];
        int r0 = __reduce_add_sync(0xffffffffu, (int)(v & 0x3FFu));          // pred
        int r1 = __reduce_add_sync(0xffffffffu, (int)((v >> 10) & 0x3FFu));  // true
        int r2 = __reduce_add_sync(0xffffffffu, (int)((v >> 20) & 0x3FFu));  // inter
        if (lane == 0) {
            scratch[warp * NB3 + c]              = r0;
            scratch[warp * NB3 + NBINS + c]      = r1;
            scratch[warp * NB3 + 2 * NBINS + c]  = r2;
        }
    }
    __syncthreads();

    // Cross-warp sum -> per-block partial in [counter][block] layout.
    if (tid < NB3) {
        int s = 0;
        #pragma unroll
        for (int w = 0; w < NWARPS; w++) s += scratch[w * NB3 + tid];
        g_part[tid * MAXBLK + blockIdx.x] = s;
    }
    __syncthreads();

    // ---- fused finalize: last block folds all partials ----
    __shared__ int is_last;
    __threadfence();
    if (tid == 0) {
        unsigned int old = atomicAdd(&g_arrive, 1u);
        is_last = (old == gridDim.x - 1) ? 1 : 0;
    }
    __syncthreads();
    if (!is_last) return;
    __threadfence();

    int*   hh   = sh;
    float* dsum = (float*)(sh + 256);
    const int nblocks = gridDim.x;

    for (int c = warp; c < NB3; c += NWARPS) {
        int s = 0;
        for (int b = lane; b < nblocks; b += 32)
            s += g_part[c * MAXBLK + b];
        s = __reduce_add_sync(0xffffffffu, s);
        if (lane == 0) hh[c] = s;
    }
    __syncthreads();

    if (tid < 64) {
        float v = 0.0f;
        if (tid >= 1 && tid < NBINS) {
            float inter = (float)hh[2 * NBINS + tid];
            float uni   = (float)hh[tid] + (float)hh[NBINS + tid];
            v = 2.0f * inter / (uni + 1e-5f);
        }
        dsum[tid] = v;
    }
    __syncthreads();

    if (tid == 0) {
        float s = 0.0f;
        #pragma unroll
        for (int i = 0; i < 64; i++) s += dsum[i];
        out[0] = 1.0f - s / (float)(NBINS - 1);
        g_arrive = 0;
    }
}

extern "C" void kernel_launch(void* const* d_in, const int* in_sizes, int n_in,
                              void* d_out, int out_size)
{
    const int* pred = (const int*)d_in[0];
    const int* targ = (const int*)d_in[1];
    const int n = in_sizes[0];

    cudaFuncSetAttribute((const void*)hist_kernel,
                         cudaFuncAttributeMaxDynamicSharedMemorySize, SMEM_BYTES);

    int sms = 148;
    if (cudaDeviceGetAttribute(&sms, cudaDevAttrMultiProcessorCount, 0) != cudaSuccess)
        sms = 148;
    int grid = sms;                            // 1 CTA/SM, 1 wave
    if (grid > MAXBLK) grid = MAXBLK;
    if (grid < 1) grid = 1;

    hist_kernel<<<grid, TPB, SMEM_BYTES>>>(pred, targ, n, (float*)d_out);
}

// round 10
// speedup vs baseline: 1.2016x; 1.1473x over previous
#include <cuda_runtime.h>
#include <cstdint>

// DiceLoss (57-bin label histogram) for B200 sm_100a — R10.
//
// R2..R9: register-resident LDG latency hiding is capped (~2.7-3.2 TB/s
// regardless of occupancy / batching / pipelining; regs=62 proved ptxas
// cannot keep a 16x LDG.128 batch live). R10 decouples the memory stream
// from registers: cp.async.cg stages int4 pairs into a 4-deep per-thread
// smem ring (fire-and-forget, no scoreboard parking, 64KB/SM in flight),
// .cg bypasses L1 allocation. Slots are thread-private -> no __syncthreads
// in the loop; per-thread cp.async.wait_group sequences stages. WAR on slot
// reuse is safe: proc4 consumes the LDS values before the refill issues.
//
// Histogram core (R9): one u32 per label per lane, 10-bit fields
//   word[v] = pred(0-9) | true(10-19) | inter(20-29)
//   pair (p,t): word[p] += (p==t) ? 0x100401 : 1; word[t] += (p==t) ? 0 : 0x400
//   (T stored first; on p==t the P store carries the combined increment.)
//   max ~222 increments/field/lane < 1023 -> no carries.
// Layout word v*32+lane -> bank==lane: conflict-free, one-IMAD address.

#define NBINS   57
#define NB3     171
#define TPB     512
#define NWARPS  16
#define STAGES  4
#define WPW     (NBINS * 32)                   // 1824 words per warp region
#define CNT_WORDS     (NWARPS * WPW)           // 29,184
#define STAGE_INT4S   (STAGES * TPB)           // per array
#define STAGE_WORDS   (STAGE_INT4S * 4 * 2)    // 16,384 (pred+targ)
#define SCRATCH_WORDS (NWARPS * NB3)           // 2736
#define SMEM_WORDS    (CNT_WORDS + STAGE_WORDS + SCRATCH_WORDS)
#define SMEM_BYTES    (SMEM_WORDS * 4)         // 193,216 B -> 1 CTA/SM
#define MAXBLK  256

__device__ int g_part[NB3 * MAXBLK];           // [counter][block]
__device__ unsigned int g_arrive = 0;          // self-resets each launch

__device__ __forceinline__ void cp16(void* smem_dst, const void* gsrc) {
    unsigned sa = (unsigned)__cvta_generic_to_shared(smem_dst);
    asm volatile("cp.async.cg.shared.global [%0], [%1], 16;" :: "r"(sa), "l"(gsrc));
}
__device__ __forceinline__ void cp_commit() {
    asm volatile("cp.async.commit_group;");
}
__device__ __forceinline__ void cp_wait3() {
    asm volatile("cp.async.wait_group 3;");
}

__device__ __forceinline__ void proc(int* wl, int p, int t) {
    int* aP = wl + (p << 5);
    int* aT = wl + (t << 5);
    bool m = (p == t);
    int incP = m ? 0x100401 : 0x000001;        // pred+true+inter | pred only
    int incT = m ? 0        : 0x000400;        // nothing         | true only
    int vP = *aP;
    int vT = *aT;
    *aT = vT + incT;       // T first; on p==t the P store lands last with the
    *aP = vP + incP;       // full combined increment -> exact.
}

__device__ __forceinline__ void proc4(int* wl, int4 a, int4 b) {
    proc(wl, a.x, b.x);
    proc(wl, a.y, b.y);
    proc(wl, a.z, b.z);
    proc(wl, a.w, b.w);
}

extern "C" __global__ void __launch_bounds__(TPB, 1)
hist_kernel(const int* __restrict__ pred, const int* __restrict__ targ, int n,
            float* __restrict__ out)
{
    extern __shared__ int sh[];
    int4* stP = (int4*)(sh + CNT_WORDS);       // [STAGES][TPB]
    int4* stT = stP + STAGE_INT4S;
    int*  scratch = sh + CNT_WORDS + STAGE_WORDS;

    const int tid  = threadIdx.x;
    const int lane = tid & 31;
    const int warp = tid >> 5;
    int* wl = sh + warp * WPW + lane;

    for (int i = tid; i < CNT_WORDS; i += TPB) sh[i] = 0;
    __syncthreads();

    const int stride4 = gridDim.x * TPB;

    const bool aligned = ((((uintptr_t)pred) | ((uintptr_t)targ)) & 15u) == 0;
    if (aligned) {
        const int n4 = n >> 2;
        const int4* __restrict__ p4 = (const int4*)pred;
        const int4* __restrict__ t4 = (const int4*)targ;
        const int base   = blockIdx.x * TPB + tid;
        const int ntrips = (n4 + stride4 - 1) / stride4;

        // prologue: fill the 4-stage ring (always commit to keep counts uniform)
        #pragma unroll
        for (int k = 0; k < STAGES; k++) {
            int idx = base + k * stride4;
            if (k < ntrips && idx < n4) {
                cp16(&stP[k * TPB + tid], p4 + idx);
                cp16(&stT[k * TPB + tid], t4 + idx);
            }
            cp_commit();
        }

        for (int k = 0; k < ntrips; k++) {
            cp_wait3();                         // stage k landed (per-thread)
            const int slot = (k & (STAGES - 1)) * TPB + tid;
            int4 a = stP[slot];
            int4 b = stT[slot];
            int idx = base + k * stride4;
            if (idx < n4) proc4(wl, a, b);      // consumes a,b before refill
            int idx2 = base + (k + STAGES) * stride4;
            if (k + STAGES < ntrips && idx2 < n4) {
                cp16(&stP[slot], p4 + idx2);
                cp16(&stT[slot], t4 + idx2);
            }
            cp_commit();
        }

        // scalar tail (n not divisible by 4)
        for (int j = (n4 << 2) + base; j < n; j += stride4)
            proc(wl, __ldg(pred + j), __ldg(targ + j));
    } else {
        for (int i = blockIdx.x * TPB + tid; i < n; i += stride4)
            proc(wl, __ldg(pred + i), __ldg(targ + i));
    }
    __syncthreads();

    // Per-warp lane reduction: 3 masked REDUX per counter.
    for (int c = 0; c < NBINS; c++) {
        unsigned int v = (unsigned int)wl[c << 5];
        int r0 = __reduce_add_sync(0xffffffffu, (int)(v & 0x3FFu));          // pred
        int r1 = __reduce_add_sync(0xffffffffu, (int)((v >> 10) & 0x3FFu));  // true
        int r2 = __reduce_add_sync(0xffffffffu, (int)((v >> 20) & 0x3FFu));  // inter
        if (lane == 0) {
            scratch[warp * NB3 + c]             = r0;
            scratch[warp * NB3 + NBINS + c]     = r1;
            scratch[warp * NB3 + 2 * NBINS + c] = r2;
        }
    }
    __syncthreads();

    // Cross-warp sum -> per-block partial, [counter][block] layout.
    if (tid < NB3) {
        int s = 0;
        #pragma unroll
        for (int w = 0; w < NWARPS; w++) s += scratch[w * NB3 + tid];
        g_part[tid * MAXBLK + blockIdx.x] = s;
    }
    __syncthreads();

    // ---- fused finalize: last block folds all partials ----
    __shared__ int is_last;
    __threadfence();
    if (tid == 0) {
        unsigned int old = atomicAdd(&g_arrive, 1u);
        is_last = (old == gridDim.x - 1) ? 1 : 0;
    }
    __syncthreads();
    if (!is_last) return;
    __threadfence();

    int*   hh   = sh;
    float* dsum = (float*)(sh + 256);
    const int nblocks = gridDim.x;

    for (int c = warp; c < NB3; c += NWARPS) {
        int s = 0;
        for (int b = lane; b < nblocks; b += 32)
            s += g_part[c * MAXBLK + b];
        s = __reduce_add_sync(0xffffffffu, s);
        if (lane == 0) hh[c] = s;
    }
    __syncthreads();

    if (tid < 64) {
        float v = 0.0f;
        if (tid >= 1 && tid < NBINS) {
            float inter = (float)hh[2 * NBINS + tid];
            float uni   = (float)hh[tid] + (float)hh[NBINS + tid];
            v = 2.0f * inter / (uni + 1e-5f);
        }
        dsum[tid] = v;
    }
    __syncthreads();

    if (tid == 0) {
        float s = 0.0f;
        #pragma unroll
        for (int i = 0; i < 64; i++) s += dsum[i];
        out[0] = 1.0f - s / (float)(NBINS - 1);
        g_arrive = 0;
    }
}

extern "C" void kernel_launch(void* const* d_in, const int* in_sizes, int n_in,
                              void* d_out, int out_size)
{
    const int* pred = (const int*)d_in[0];
    const int* targ = (const int*)d_in[1];
    const int n = in_sizes[0];

    cudaFuncSetAttribute((const void*)hist_kernel,
                         cudaFuncAttributeMaxDynamicSharedMemorySize, SMEM_BYTES);

    int sms = 148;
    if (cudaDeviceGetAttribute(&sms, cudaDevAttrMultiProcessorCount, 0) != cudaSuccess)
        sms = 148;
    int grid = sms;                             // 1 CTA/SM, single wave
    if (grid > MAXBLK) grid = MAXBLK;
    if (grid < 1) grid = 1;

    hist_kernel<<<grid, TPB, SMEM_BYTES>>>(pred, targ, n, (float*)d_out);
}

// round 11
// speedup vs baseline: 1.2510x; 1.0411x over previous
#include <cuda_runtime.h>
#include <cstdint>

// DiceLoss (57-bin label histogram) for B200 sm_100a — R11.
//
// R10 (per-thread cp.async ring) reached 3.25 TB/s but each trip had ~900
// dead cycles: per-warp wait_group parking + 2 cp ops/thread of LSU traffic.
// R11 moves the copy off the warps entirely: ONE thread issues cp.async.bulk
// (8KB pred + 8KB targ) per pipeline stage into a 4-deep smem ring; completion
// is an mbarrier complete_tx (16KB). The bulk/TMA engine streams independently
// of warp scheduling: no per-thread copy instructions, no scoreboard parking,
// 64KB/SM in flight. Consumers try_wait.parity(acquire) on the stage barrier,
// each thread processes its own int4 pair, __syncthreads, slot refilled.
//
// Histogram core (R9): one u32 per label per lane, 10-bit fields
//   word[v] = pred(0-9) | true(10-19) | inter(20-29)
//   pair (p,t): word[p] += (p==t) ? 0x100401 : 1; word[t] += (p==t) ? 0 : 0x400
//   (T stored first; on p==t the P store lands last with the full increment.)
//   max ~222 increments/field/lane < 1023 -> no carries.
// Layout word v*32+lane -> bank==lane: conflict-free, one-IMAD address.

#define NBINS   57
#define NB3     171
#define TPB     512
#define NWARPS  16
#define STAGES  4
#define TILE_I4 512                              // int4s per array per tile
#define TILE_BYTES (TILE_I4 * 16)                // 8192
#define WPW     (NBINS * 32)                     // 1824 words per warp region
#define CNT_WORDS     (NWARPS * WPW)             // 29,184
#define STAGE_WORDS   (STAGES * TILE_I4 * 4 * 2) // 16,384 (pred+targ)
#define SCRATCH_WORDS (NWARPS * NB3)             // 2736
#define MBAR_WORDS    8                          // 4 barriers x 8B
#define SMEM_WORDS    (CNT_WORDS + STAGE_WORDS + SCRATCH_WORDS + MBAR_WORDS)
#define SMEM_BYTES    (SMEM_WORDS * 4)           // 193,248 B -> 1 CTA/SM
#define MAXBLK  256

__device__ int g_part[NB3 * MAXBLK];             // [counter][block]
__device__ unsigned int g_arrive = 0;            // self-resets each launch

__device__ __forceinline__ unsigned smem_u32(const void* p) {
    return (unsigned)__cvta_generic_to_shared(p);
}
__device__ __forceinline__ void mbar_init(unsigned mbar, unsigned count) {
    asm volatile("mbarrier.init.shared.b64 [%0], %1;" :: "r"(mbar), "r"(count) : "memory");
}
__device__ __forceinline__ void mbar_expect_tx(unsigned mbar, unsigned tx) {
    asm volatile("mbarrier.arrive.expect_tx.shared.b64 _, [%0], %1;" :: "r"(mbar), "r"(tx) : "memory");
}
__device__ __forceinline__ void bulk_g2s(unsigned sdst, const void* gsrc,
                                         unsigned bytes, unsigned mbar) {
    asm volatile("cp.async.bulk.shared::cta.global.mbarrier::complete_tx::bytes "
                 "[%0], [%1], %2, [%3];"
                 :: "r"(sdst), "l"(gsrc), "r"(bytes), "r"(mbar) : "memory");
}
__device__ __forceinline__ void mbar_wait(unsigned mbar, unsigned phase) {
    asm volatile(
        "{\n\t.reg .pred p;\n\t"
        "WAIT_%=:\n\t"
        "mbarrier.try_wait.parity.acquire.cta.shared::cta.b64 p, [%0], %1, 0x989680;\n\t"
        "@!p bra WAIT_%=;\n\t}"
        :: "r"(mbar), "r"(phase) : "memory");
}

__device__ __forceinline__ void proc(int* wl, int p, int t) {
    int* aP = wl + (p << 5);
    int* aT = wl + (t << 5);
    bool m = (p == t);
    int incP = m ? 0x100401 : 0x000001;          // pred+true+inter | pred only
    int incT = m ? 0        : 0x000400;          // nothing         | true only
    int vP = *aP;
    int vT = *aT;
    *aT = vT + incT;        // T first; on p==t the P store lands last with the
    *aP = vP + incP;        // full combined increment -> exact.
}

__device__ __forceinline__ void proc4(int* wl, int4 a, int4 b) {
    proc(wl, a.x, b.x);
    proc(wl, a.y, b.y);
    proc(wl, a.z, b.z);
    proc(wl, a.w, b.w);
}

extern "C" __global__ void __launch_bounds__(TPB, 1)
hist_kernel(const int* __restrict__ pred, const int* __restrict__ targ, int n,
            float* __restrict__ out)
{
    extern __shared__ int sh[];
    int4* stP = (int4*)(sh + CNT_WORDS);         // [STAGES][TILE_I4]
    int4* stT = stP + STAGES * TILE_I4;
    int*  scratch = sh + CNT_WORDS + STAGE_WORDS;
    long long* mbar_mem = (long long*)(sh + CNT_WORDS + STAGE_WORDS + SCRATCH_WORDS);

    const int tid  = threadIdx.x;
    const int lane = tid & 31;
    const int warp = tid >> 5;
    int* wl = sh + warp * WPW + lane;
    const unsigned mb0 = smem_u32(mbar_mem);

    for (int i = tid; i < CNT_WORDS; i += TPB) sh[i] = 0;
    if (tid == 0) {
        #pragma unroll
        for (int s = 0; s < STAGES; s++) mbar_init(mb0 + 8 * s, 1);
    }
    __syncthreads();

    const int grid = gridDim.x;
    const int stride1 = grid * TPB;

    const bool aligned = ((((uintptr_t)pred) | ((uintptr_t)targ)) & 15u) == 0;
    if (aligned) {
        const int n4 = n >> 2;
        const int ntiles = n4 / TILE_I4;         // full 8KB tiles per array
        const int4* __restrict__ p4 = (const int4*)pred;
        const int4* __restrict__ t4 = (const int4*)targ;

        // prologue: issue first STAGES tiles for this block
        if (tid == 0) {
            #pragma unroll
            for (int k = 0; k < STAGES; k++) {
                int tile = blockIdx.x + k * grid;
                if (tile < ntiles) {
                    unsigned mb = mb0 + 8 * k;
                    mbar_expect_tx(mb, 2 * TILE_BYTES);
                    bulk_g2s(smem_u32(&stP[k * TILE_I4]), p4 + (size_t)tile * TILE_I4,
                             TILE_BYTES, mb);
                    bulk_g2s(smem_u32(&stT[k * TILE_I4]), t4 + (size_t)tile * TILE_I4,
                             TILE_BYTES, mb);
                }
            }
        }

        int trip = 0;
        for (int tile = blockIdx.x; tile < ntiles; tile += grid, trip++) {
            const int slot  = trip & (STAGES - 1);
            const unsigned phase = (trip >> 2) & 1u;
            mbar_wait(mb0 + 8 * slot, phase);
            int4 a = stP[slot * TILE_I4 + tid];
            int4 b = stT[slot * TILE_I4 + tid];
            proc4(wl, a, b);
            __syncthreads();                     // all consumed -> slot reusable
            int tile2 = tile + STAGES * grid;
            if (tid == 0 && tile2 < ntiles) {
                unsigned mb = mb0 + 8 * slot;
                mbar_expect_tx(mb, 2 * TILE_BYTES);
                bulk_g2s(smem_u32(&stP[slot * TILE_I4]), p4 + (size_t)tile2 * TILE_I4,
                         TILE_BYTES, mb);
                bulk_g2s(smem_u32(&stT[slot * TILE_I4]), t4 + (size_t)tile2 * TILE_I4,
                         TILE_BYTES, mb);
            }
        }

        // remainder ints beyond full tiles
        for (int j = ntiles * TILE_I4 * 4 + blockIdx.x * TPB + tid; j < n; j += stride1)
            proc(wl, __ldg(pred + j), __ldg(targ + j));
    } else {
        for (int i = blockIdx.x * TPB + tid; i < n; i += stride1)
            proc(wl, __ldg(pred + i), __ldg(targ + i));
    }
    __syncthreads();

    // Per-warp lane reduction: 3 masked REDUX per counter.
    for (int c = 0; c < NBINS; c++) {
        unsigned int v = (unsigned int)wl[c << 5];
        int r0 = __reduce_add_sync(0xffffffffu, (int)(v & 0x3FFu));          // pred
        int r1 = __reduce_add_sync(0xffffffffu, (int)((v >> 10) & 0x3FFu));  // true
        int r2 = __reduce_add_sync(0xffffffffu, (int)((v >> 20) & 0x3FFu));  // inter
        if (lane == 0) {
            scratch[warp * NB3 + c]             = r0;
            scratch[warp * NB3 + NBINS + c]     = r1;
            scratch[warp * NB3 + 2 * NBINS + c] = r2;
        }
    }
    __syncthreads();

    // Cross-warp sum -> per-block partial, [counter][block] layout.
    if (tid < NB3) {
        int s = 0;
        #pragma unroll
        for (int w = 0; w < NWARPS; w++) s += scratch[w * NB3 + tid];
        g_part[tid * MAXBLK + blockIdx.x] = s;
    }
    __syncthreads();

    // ---- fused finalize: last block folds all partials ----
    __shared__ int is_last;
    __threadfence();
    if (tid == 0) {
        unsigned int old = atomicAdd(&g_arrive, 1u);
        is_last = (old == gridDim.x - 1) ? 1 : 0;
    }
    __syncthreads();
    if (!is_last) return;
    __threadfence();

    int*   hh   = sh;
    float* dsum = (float*)(sh + 256);
    const int nblocks = gridDim.x;

    for (int c = warp; c < NB3; c += NWARPS) {
        int s = 0;
        for (int b = lane; b < nblocks; b += 32)
            s += g_part[c * MAXBLK + b];
        s = __reduce_add_sync(0xffffffffu, s);
        if (lane == 0) hh[c] = s;
    }
    __syncthreads();

    if (tid < 64) {
        float v = 0.0f;
        if (tid >= 1 && tid < NBINS) {
            float inter = (float)hh[2 * NBINS + tid];
            float uni   = (float)hh[tid] + (float)hh[NBINS + tid];
            v = 2.0f * inter / (uni + 1e-5f);
        }
        dsum[tid] = v;
    }
    __syncthreads();

    if (tid == 0) {
        float s = 0.0f;
        #pragma unroll
        for (int i = 0; i < 64; i++) s += dsum[i];
        out[0] = 1.0f - s / (float)(NBINS - 1);
        g_arrive = 0;
    }
}

extern "C" void kernel_launch(void* const* d_in, const int* in_sizes, int n_in,
                              void* d_out, int out_size)
{
    const int* pred = (const int*)d_in[0];
    const int* targ = (const int*)d_in[1];
    const int n = in_sizes[0];

    cudaFuncSetAttribute((const void*)hist_kernel,
                         cudaFuncAttributeMaxDynamicSharedMemorySize, SMEM_BYTES);

    int sms = 148;
    if (cudaDeviceGetAttribute(&sms, cudaDevAttrMultiProcessorCount, 0) != cudaSuccess)
        sms = 148;
    int grid = sms;                              // 1 CTA/SM, single wave
    if (grid > MAXBLK) grid = MAXBLK;
    if (grid < 1) grid = 1;

    hist_kernel<<<grid, TPB, SMEM_BYTES>>>(pred, targ, n, (float*)d_out);
}